// round 15
// baseline (speedup 1.0000x reference)
#include <cuda_runtime.h>
#include <math.h>

// Problem constants (fixed by the dataset)
#define NE 4096
#define NW 8192
#define KD 128
#define GG 1024
#define MM 64
#define JJ 256

#define NBLK 1184    // 148 SMs * 8 blocks
#define NTHR 256
#define TPT 512      // transpose tiles: (128/32 k) * (8192/64 n)

// Skewed static streaming split (512*XS + 672*YS == 8388608 == NE*NW/4)
#define XS 6430      // float4 share for transpose-first blocks (0..511)
#define YS 7584      // float4 share for pure-stream blocks (512..1183)

// Scratch (device globals — no runtime allocation allowed)
__device__ float g_Wt[NW * KD];    // transposed W (4 MB)
__device__ float g_pwt[TPT];       // per-tile relu(W)^2 partials
__device__ float g_pr[NBLK];       // per-block (a-p)^2 partials
__device__ float g_pe[NBLK];       // per-block relu(E)^2 partials
__device__ float g_sim[GG];        // per-group word sim term
__device__ float g_ent[2];         // entity term
__device__ int   g_prep = 0;       // transpose-done counter (reset by compose)

__device__ __forceinline__ float block_reduce(float v) {
    __shared__ float sh[32];
    int lane = threadIdx.x & 31;
    int wid  = threadIdx.x >> 5;
    #pragma unroll
    for (int o = 16; o > 0; o >>= 1) v += __shfl_down_sync(0xffffffffu, v, o);
    __syncthreads();
    if (lane == 0) sh[wid] = v;
    __syncthreads();
    v = (threadIdx.x < (NTHR >> 5)) ? sh[threadIdx.x] : 0.0f;
    if (wid == 0) {
        #pragma unroll
        for (int o = 16; o > 0; o >>= 1) v += __shfl_down_sync(0xffffffffu, v, o);
    }
    return v;   // valid in thread 0
}

// ---------------------------------------------------------------------------
// K_A: fused transpose + streaming reduce (R14 form, proven).
// Blocks 0..TPT-1 transpose one tile first (fused relu(W)^2), signal g_prep,
// then stream a SMALLER share; blocks TPT.. stream a LARGER share.
// ---------------------------------------------------------------------------
__global__ void __launch_bounds__(NTHR, 8)
fusedstream_k(const float* __restrict__ actual,
              const float* __restrict__ pred,
              const float* __restrict__ W,
              const float* __restrict__ E) {
    asm volatile("griddepcontrol.launch_dependents;");

    const int b = blockIdx.x;
    const int t = threadIdx.x;

    int s4, e4v;   // this block's contiguous float4 range in a/p

    if (b < TPT) {
        // ---- transpose one 32k x 64n tile of W into g_Wt, fused relu^2 ----
        __shared__ float s[64][33];
        const int tk = (b & 3) * 32;         // k base
        const int tn = (b >> 2) * 64;        // n base
        const float4* W4 = (const float4*)W;

        const int kk = t >> 4;               // 0..15
        const int ff = t & 15;               // 0..15
        float wacc = 0.0f;
        #pragma unroll
        for (int p = 0; p < 2; p++) {
            const int k = tk + kk + p * 16;
            float4 v = W4[(size_t)k * (NW / 4) + (tn >> 2) + ff];
            const int nl = ff * 4;
            const int kl = kk + p * 16;
            s[nl + 0][kl] = v.x;
            s[nl + 1][kl] = v.y;
            s[nl + 2][kl] = v.z;
            s[nl + 3][kl] = v.w;
            float r;
            r = fmaxf(v.x, 0.f); wacc += r * r;
            r = fmaxf(v.y, 0.f); wacc += r * r;
            r = fmaxf(v.z, 0.f); wacc += r * r;
            r = fmaxf(v.w, 0.f); wacc += r * r;
        }
        __syncthreads();

        float4* Wt4 = (float4*)g_Wt;
        const int nl = t >> 3;               // 0..31
        const int f  = t & 7;                // 0..7
        #pragma unroll
        for (int p = 0; p < 2; p++) {
            const int n = nl + p * 32;
            float4 o;
            o.x = s[n][4 * f + 0];
            o.y = s[n][4 * f + 1];
            o.z = s[n][4 * f + 2];
            o.w = s[n][4 * f + 3];
            Wt4[(size_t)(tn + n) * (KD / 4) + (tk >> 2) + f] = o;
        }

        float wsum = block_reduce(wacc);
        if (t == 0) g_pwt[b] = wsum;

        __threadfence();                 // release Wt tile (runs once, hidden)
        if (t == 0) atomicAdd(&g_prep, 1);
        __syncthreads();

        s4  = b * XS;
        e4v = s4 + XS;
    } else {
        s4  = TPT * XS + (b - TPT) * YS;
        e4v = s4 + YS;
    }

    // ---- streaming reduce over this block's contiguous range ----
    const float4* a4 = (const float4*)actual;
    const float4* p4 = (const float4*)pred;

    float s0 = 0.f, s1 = 0.f, s2 = 0.f, s3 = 0.f;
    int i = s4 + t;
    for (; i + 3 * NTHR < e4v; i += 4 * NTHR) {
        float4 av0 = a4[i];
        float4 av1 = a4[i +     NTHR];
        float4 av2 = a4[i + 2 * NTHR];
        float4 av3 = a4[i + 3 * NTHR];
        float4 pv0 = p4[i];
        float4 pv1 = p4[i +     NTHR];
        float4 pv2 = p4[i + 2 * NTHR];
        float4 pv3 = p4[i + 3 * NTHR];
        float d;
        d = av0.x - pv0.x; s0 += d * d; d = av0.y - pv0.y; s0 += d * d;
        d = av0.z - pv0.z; s0 += d * d; d = av0.w - pv0.w; s0 += d * d;
        d = av1.x - pv1.x; s1 += d * d; d = av1.y - pv1.y; s1 += d * d;
        d = av1.z - pv1.z; s1 += d * d; d = av1.w - pv1.w; s1 += d * d;
        d = av2.x - pv2.x; s2 += d * d; d = av2.y - pv2.y; s2 += d * d;
        d = av2.z - pv2.z; s2 += d * d; d = av2.w - pv2.w; s2 += d * d;
        d = av3.x - pv3.x; s3 += d * d; d = av3.y - pv3.y; s3 += d * d;
        d = av3.z - pv3.z; s3 += d * d; d = av3.w - pv3.w; s3 += d * d;
    }
    for (; i < e4v; i += NTHR) {
        float4 av = a4[i];
        float4 pv = p4[i];
        float d;
        d = av.x - pv.x; s0 += d * d; d = av.y - pv.y; s0 += d * d;
        d = av.z - pv.z; s0 += d * d; d = av.w - pv.w; s0 += d * d;
    }
    float s_r = (s0 + s1) + (s2 + s3);

    // ---- relu(E)^2 (tiny, grid-strided over all blocks) ----
    float s_e = 0.0f;
    {
        const float4* e4 = (const float4*)E;
        const int ne4 = (NE * KD) / 4;
        for (int q = b * NTHR + t; q < ne4; q += NBLK * NTHR) {
            float4 v = e4[q];
            float r0 = fmaxf(v.x, 0.f), r1 = fmaxf(v.y, 0.f);
            float r2 = fmaxf(v.z, 0.f), r3 = fmaxf(v.w, 0.f);
            s_e += r0 * r0 + r1 * r1 + r2 * r2 + r3 * r3;
        }
    }

    float br = block_reduce(s_r);
    __syncthreads();
    float be = block_reduce(s_e);
    if (t == 0) {
        g_pr[b] = br;
        g_pe[b] = be;
    }
}

// ---------------------------------------------------------------------------
// K_B (PDL after K_A): GG gather blocks + 1 entity block.
// NO ticket, NO atomics, NO all-thread fences — blocks just write g_sim /
// g_ent and exit. Kernel-boundary stream ordering gives K_C visibility.
// Only the t0 g_prep guard remains (K_B may start while K_A still runs).
// ---------------------------------------------------------------------------
__global__ void __launch_bounds__(NTHR)
gather_k(const float* __restrict__ Sw,
         const float* __restrict__ E,
         const float* __restrict__ Se,
         const int*   __restrict__ rowi,
         const int*   __restrict__ wi,
         const int*   __restrict__ ej,
         const int*   __restrict__ sj) {
    const int b = blockIdx.x;     // 0..GG (GG = entity block)
    const int t = threadIdx.x;

    if (b < GG) {
        __shared__ int idxs[MM];
        const int j = sj[b];
        if (t < MM) idxs[t] = wi[b * MM + t];
        __syncthreads();
        float swv = (t < MM) ? Sw[(size_t)j * NW + idxs[t]] : 0.0f;

        // guard: transpose must be complete (t0-only; cheap)
        if (t == 0) {
            if (*(volatile int*)&g_prep < TPT) {
                do { __nanosleep(64); } while (*(volatile int*)&g_prep < TPT);
            }
            __threadfence();   // acquire g_Wt
        }
        __syncthreads();

        const int k    = t & (KD - 1);
        const int half = t >> 7;
        const float wjk = g_Wt[(size_t)j * KD + k];

        float a0 = 0.0f, a1 = 0.0f;
        const int m0 = half * (MM / 2);
        #pragma unroll
        for (int m = 0; m < MM / 2; m += 2) {
            float d0 = wjk - g_Wt[(size_t)idxs[m0 + m]     * KD + k];
            float d1 = wjk - g_Wt[(size_t)idxs[m0 + m + 1] * KD + k];
            a0 += d0 * d0;
            a1 += d1 * d1;
        }

        float d2 = block_reduce(a0 + a1);
        __syncthreads();
        float sw = block_reduce(swv);
        if (t == 0) g_sim[b] = sqrtf(d2) * sw;
    } else {
        __shared__ int ejs[JJ];
        const int row_i = rowi[0];
        if (t < JJ) ejs[t] = ej[t];
        __syncthreads();
        float s_de = 0.0f;
        for (int i = t; i < JJ * KD; i += NTHR) {
            int jj = i >> 7;
            int kk = i & (KD - 1);
            float d = E[(size_t)row_i * KD + kk] - E[(size_t)ejs[jj] * KD + kk];
            s_de += d * d;
        }
        float s_se = (t < JJ) ? Se[(size_t)row_i * NE + ejs[t]] : 0.0f;
        float de = block_reduce(s_de);
        __syncthreads();
        float se = block_reduce(s_se);
        if (t == 0) { g_ent[0] = de; g_ent[1] = se; }
    }
}

// ---------------------------------------------------------------------------
// K_C: compose (1 block). Plain launch — stream order after K_B (and
// transitively K_A) makes all partials visible with zero waits/fences.
// Fixed-order reduction -> deterministic. Resets g_prep for graph replay.
// ---------------------------------------------------------------------------
__global__ void __launch_bounds__(NTHR)
compose_k(const float* __restrict__ lamb, float* __restrict__ out) {
    const int t = threadIdx.x;

    float sr = 0.f, sw2 = 0.f, se = 0.f, sim = 0.f;
    for (int q = t; q < NBLK; q += NTHR) {
        sr += g_pr[q];
        se += g_pe[q];
    }
    for (int q = t; q < TPT; q += NTHR) sw2 += g_pwt[q];
    for (int q = t; q < GG; q += NTHR) sim += g_sim[q];

    float Sr  = block_reduce(sr);   __syncthreads();
    float Sw_ = block_reduce(sw2);  __syncthreads();
    float Se_ = block_reduce(se);   __syncthreads();
    float Sim = block_reduce(sim);

    if (t == 0) {
        float recon = sqrtf(Sr);
        float param = sqrtf(Sw_) + sqrtf(Se_);
        float sim_p = Sim + sqrtf(g_ent[0]) * g_ent[1];
        out[0] = recon + lamb[0] * param + sim_p;
        g_prep = 0;    // reset for next graph replay
    }
}

// ---------------------------------------------------------------------------
// Launch: K_A (fused transpose+stream) -> K_B (PDL gather) -> K_C (compose).
// Inputs (metadata order):
//  0 actual  1 prediction  2 W  3 E  4 Sw  5 Se  6 lamb  7 row_ind
//  8 word_i_indices  9 entity_j_indices  10 sample_j_indices
// ---------------------------------------------------------------------------
extern "C" void kernel_launch(void* const* d_in, const int* in_sizes, int n_in,
                              void* d_out, int out_size) {
    const float* actual = (const float*)d_in[0];
    const float* pred   = (const float*)d_in[1];
    const float* W      = (const float*)d_in[2];
    const float* E      = (const float*)d_in[3];
    const float* Sw     = (const float*)d_in[4];
    const float* Se     = (const float*)d_in[5];
    const float* lamb   = (const float*)d_in[6];
    const int*   rowi   = (const int*)  d_in[7];
    const int*   wi     = (const int*)  d_in[8];
    const int*   ej     = (const int*)  d_in[9];
    const int*   sj     = (const int*)  d_in[10];
    float* out = (float*)d_out;

    fusedstream_k<<<NBLK, NTHR>>>(actual, pred, W, E);

    cudaLaunchAttribute pdl[1];
    pdl[0].id = cudaLaunchAttributeProgrammaticStreamSerialization;
    pdl[0].val.programmaticStreamSerializationAllowed = 1;

    {
        cudaLaunchConfig_t cfg = {};
        cfg.gridDim  = dim3(GG + 1, 1, 1);
        cfg.blockDim = dim3(NTHR, 1, 1);
        cfg.dynamicSmemBytes = 0;
        cfg.stream = (cudaStream_t)0;
        cfg.attrs = pdl;
        cfg.numAttrs = 1;
        cudaLaunchKernelEx(&cfg, gather_k, Sw, E, Se, rowi, wi, ej, sj);
    }

    compose_k<<<1, NTHR>>>(lamb, out);
}

// round 16
// speedup vs baseline: 1.1176x; 1.1176x over previous
#include <cuda_runtime.h>
#include <math.h>

// Problem constants (fixed by the dataset)
#define NE 4096
#define NW 8192
#define KD 128
#define GG 1024
#define MM 64
#define JJ 256

#define NBLK 1184    // 148 SMs * 8 blocks
#define NTHR 256
#define TPT 512      // transpose tiles: (128/32 k) * (8192/64 n)

// Skewed static streaming split (512*XS + 672*YS == 8388608 == NE*NW/4)
#define XS 6556      // float4 share for transpose-first blocks (0..511)
#define YS 7488      // float4 share for pure-stream blocks (512..1183)

// Scratch (device globals — no runtime allocation allowed)
__device__ float g_Wt[NW * KD];    // transposed W (4 MB, L2-resident)
__device__ float g_pwt[TPT];       // per-tile relu(W)^2 partials
__device__ float g_pr[NBLK];       // per-block (a-p)^2 partials
__device__ float g_pe[NBLK];       // per-block relu(E)^2 partials
__device__ float g_sim[GG];        // per-group word sim term
__device__ float g_ent[2];         // entity term
__device__ int   g_prep = 0;       // transpose-done counter (reset by compose)
__device__ int   g_done = 0;       // gather ticket          (reset by compose)

__device__ __forceinline__ float block_reduce(float v) {
    __shared__ float sh[32];
    int lane = threadIdx.x & 31;
    int wid  = threadIdx.x >> 5;
    #pragma unroll
    for (int o = 16; o > 0; o >>= 1) v += __shfl_down_sync(0xffffffffu, v, o);
    __syncthreads();
    if (lane == 0) sh[wid] = v;
    __syncthreads();
    v = (threadIdx.x < (NTHR >> 5)) ? sh[threadIdx.x] : 0.0f;
    if (wid == 0) {
        #pragma unroll
        for (int o = 16; o > 0; o >>= 1) v += __shfl_down_sync(0xffffffffu, v, o);
    }
    return v;   // valid in thread 0
}

// ---------------------------------------------------------------------------
// K_A: fused transpose + streaming reduce.
// Blocks 0..TPT-1 transpose one tile first (fused relu(W)^2), signal g_prep,
// then stream a SMALLER share; blocks TPT.. stream a LARGER share.
// a/p loads use __ldcs (evict-first): zero reuse, and keeps g_Wt in L2 for
// the gather (R7-vs-R8 controlled pair favored ldcs).
// ---------------------------------------------------------------------------
__global__ void __launch_bounds__(NTHR, 8)
fusedstream_k(const float* __restrict__ actual,
              const float* __restrict__ pred,
              const float* __restrict__ W,
              const float* __restrict__ E) {
    asm volatile("griddepcontrol.launch_dependents;");

    const int b = blockIdx.x;
    const int t = threadIdx.x;

    int s4, e4v;   // this block's contiguous float4 range in a/p

    if (b < TPT) {
        // ---- transpose one 32k x 64n tile of W into g_Wt, fused relu^2 ----
        __shared__ float s[64][33];
        const int tk = (b & 3) * 32;         // k base
        const int tn = (b >> 2) * 64;        // n base
        const float4* W4 = (const float4*)W;

        const int kk = t >> 4;               // 0..15
        const int ff = t & 15;               // 0..15
        float wacc = 0.0f;
        #pragma unroll
        for (int p = 0; p < 2; p++) {
            const int k = tk + kk + p * 16;
            float4 v = W4[(size_t)k * (NW / 4) + (tn >> 2) + ff];
            const int nl = ff * 4;
            const int kl = kk + p * 16;
            s[nl + 0][kl] = v.x;
            s[nl + 1][kl] = v.y;
            s[nl + 2][kl] = v.z;
            s[nl + 3][kl] = v.w;
            float r;
            r = fmaxf(v.x, 0.f); wacc += r * r;
            r = fmaxf(v.y, 0.f); wacc += r * r;
            r = fmaxf(v.z, 0.f); wacc += r * r;
            r = fmaxf(v.w, 0.f); wacc += r * r;
        }
        __syncthreads();

        float4* Wt4 = (float4*)g_Wt;
        const int nl = t >> 3;               // 0..31
        const int f  = t & 7;                // 0..7
        #pragma unroll
        for (int p = 0; p < 2; p++) {
            const int n = nl + p * 32;
            float4 o;
            o.x = s[n][4 * f + 0];
            o.y = s[n][4 * f + 1];
            o.z = s[n][4 * f + 2];
            o.w = s[n][4 * f + 3];
            Wt4[(size_t)(tn + n) * (KD / 4) + (tk >> 2) + f] = o;
        }

        float wsum = block_reduce(wacc);
        if (t == 0) g_pwt[b] = wsum;

        __threadfence();                 // release Wt tile
        if (t == 0) atomicAdd(&g_prep, 1);
        __syncthreads();

        s4  = b * XS;
        e4v = s4 + XS;
    } else {
        s4  = TPT * XS + (b - TPT) * YS;
        e4v = s4 + YS;
    }

    // ---- streaming reduce over this block's contiguous range ----
    const float4* a4 = (const float4*)actual;
    const float4* p4 = (const float4*)pred;

    float s0 = 0.f, s1 = 0.f, s2 = 0.f, s3 = 0.f;
    int i = s4 + t;
    for (; i + 3 * NTHR < e4v; i += 4 * NTHR) {
        float4 av0 = __ldcs(&a4[i]);
        float4 av1 = __ldcs(&a4[i +     NTHR]);
        float4 av2 = __ldcs(&a4[i + 2 * NTHR]);
        float4 av3 = __ldcs(&a4[i + 3 * NTHR]);
        float4 pv0 = __ldcs(&p4[i]);
        float4 pv1 = __ldcs(&p4[i +     NTHR]);
        float4 pv2 = __ldcs(&p4[i + 2 * NTHR]);
        float4 pv3 = __ldcs(&p4[i + 3 * NTHR]);
        float d;
        d = av0.x - pv0.x; s0 += d * d; d = av0.y - pv0.y; s0 += d * d;
        d = av0.z - pv0.z; s0 += d * d; d = av0.w - pv0.w; s0 += d * d;
        d = av1.x - pv1.x; s1 += d * d; d = av1.y - pv1.y; s1 += d * d;
        d = av1.z - pv1.z; s1 += d * d; d = av1.w - pv1.w; s1 += d * d;
        d = av2.x - pv2.x; s2 += d * d; d = av2.y - pv2.y; s2 += d * d;
        d = av2.z - pv2.z; s2 += d * d; d = av2.w - pv2.w; s2 += d * d;
        d = av3.x - pv3.x; s3 += d * d; d = av3.y - pv3.y; s3 += d * d;
        d = av3.z - pv3.z; s3 += d * d; d = av3.w - pv3.w; s3 += d * d;
    }
    for (; i < e4v; i += NTHR) {
        float4 av = __ldcs(&a4[i]);
        float4 pv = __ldcs(&p4[i]);
        float d;
        d = av.x - pv.x; s0 += d * d; d = av.y - pv.y; s0 += d * d;
        d = av.z - pv.z; s0 += d * d; d = av.w - pv.w; s0 += d * d;
    }
    float s_r = (s0 + s1) + (s2 + s3);

    // ---- relu(E)^2 (tiny, grid-strided over all blocks) ----
    float s_e = 0.0f;
    {
        const float4* e4 = (const float4*)E;
        const int ne4 = (NE * KD) / 4;
        for (int q = b * NTHR + t; q < ne4; q += NBLK * NTHR) {
            float4 v = e4[q];
            float r0 = fmaxf(v.x, 0.f), r1 = fmaxf(v.y, 0.f);
            float r2 = fmaxf(v.z, 0.f), r3 = fmaxf(v.w, 0.f);
            s_e += r0 * r0 + r1 * r1 + r2 * r2 + r3 * r3;
        }
    }

    float br = block_reduce(s_r);
    __syncthreads();
    float be = block_reduce(s_e);
    if (t == 0) {
        g_pr[b] = br;
        g_pe[b] = be;
    }
}

// ---------------------------------------------------------------------------
// K_B (PDL after K_A): GG gather blocks + 1 entity block + merged compose.
// Per-block cost of the ticket is ONE t0 fence + ONE t0 atomic (the R14
// 26us came from all-thread fences, which stay removed). The ticket-elected
// last block runs griddepcontrol.wait (K_A partials) and composes.
// ---------------------------------------------------------------------------
__global__ void __launch_bounds__(NTHR)
gather_k(const float* __restrict__ Sw,
         const float* __restrict__ E,
         const float* __restrict__ Se,
         const float* __restrict__ lamb,
         const int*   __restrict__ rowi,
         const int*   __restrict__ wi,
         const int*   __restrict__ ej,
         const int*   __restrict__ sj,
         float* __restrict__ out) {
    const int b = blockIdx.x;     // 0..GG (GG = entity block)
    const int t = threadIdx.x;

    if (b < GG) {
        __shared__ int idxs[MM];
        const int j = sj[b];
        if (t < MM) idxs[t] = wi[b * MM + t];
        __syncthreads();
        float swv = (t < MM) ? Sw[(size_t)j * NW + idxs[t]] : 0.0f;

        // guard: transpose must be complete (t0-only; nearly always true)
        if (t == 0) {
            if (*(volatile int*)&g_prep < TPT) {
                do { __nanosleep(64); } while (*(volatile int*)&g_prep < TPT);
            }
            __threadfence();   // acquire g_Wt
        }
        __syncthreads();

        const int k    = t & (KD - 1);
        const int half = t >> 7;
        const float wjk = g_Wt[(size_t)j * KD + k];

        float a0 = 0.0f, a1 = 0.0f;
        const int m0 = half * (MM / 2);
        #pragma unroll
        for (int m = 0; m < MM / 2; m += 2) {
            float d0 = wjk - g_Wt[(size_t)idxs[m0 + m]     * KD + k];
            float d1 = wjk - g_Wt[(size_t)idxs[m0 + m + 1] * KD + k];
            a0 += d0 * d0;
            a1 += d1 * d1;
        }

        float d2 = block_reduce(a0 + a1);
        __syncthreads();
        float sw = block_reduce(swv);
        if (t == 0) g_sim[b] = sqrtf(d2) * sw;
    } else {
        __shared__ int ejs[JJ];
        const int row_i = rowi[0];
        if (t < JJ) ejs[t] = ej[t];
        __syncthreads();
        float s_de = 0.0f;
        for (int i = t; i < JJ * KD; i += NTHR) {
            int jj = i >> 7;
            int kk = i & (KD - 1);
            float d = E[(size_t)row_i * KD + kk] - E[(size_t)ejs[jj] * KD + kk];
            s_de += d * d;
        }
        float s_se = (t < JJ) ? Se[(size_t)row_i * NE + ejs[t]] : 0.0f;
        float de = block_reduce(s_de);
        __syncthreads();
        float se = block_reduce(s_se);
        if (t == 0) { g_ent[0] = de; g_ent[1] = se; }
    }

    // ---- t0-only release + ticket ----
    __shared__ int amLast;
    if (t == 0) {
        __threadfence();                    // release g_sim / g_ent
        int r = atomicAdd(&g_done, 1);
        amLast = (r == GG);                 // GG+1 blocks total
    }
    __syncthreads();

    if (amLast) {
        // K_A grid completion => g_pr/g_pe/g_pwt visible.
        asm volatile("griddepcontrol.wait;");
        if (t == 0) __threadfence();        // acquire other blocks' writes
        __syncthreads();

        float sr = 0.f, sw2 = 0.f, se = 0.f, sim = 0.f;
        for (int q = t; q < NBLK; q += NTHR) {
            sr += g_pr[q];
            se += g_pe[q];
        }
        for (int q = t; q < TPT; q += NTHR) sw2 += g_pwt[q];
        for (int q = t; q < GG; q += NTHR) sim += g_sim[q];

        float Sr  = block_reduce(sr);   __syncthreads();
        float Sw_ = block_reduce(sw2);  __syncthreads();
        float Se_ = block_reduce(se);   __syncthreads();
        float Sim = block_reduce(sim);

        if (t == 0) {
            float recon = sqrtf(Sr);
            float param = sqrtf(Sw_) + sqrtf(Se_);
            float sim_p = Sim + sqrtf(g_ent[0]) * g_ent[1];
            out[0] = recon + lamb[0] * param + sim_p;
            g_done = 0;    // reset for next graph replay
            g_prep = 0;
        }
    }
}

// ---------------------------------------------------------------------------
// Launch: K_A (fused transpose+stream) -> K_B (PDL gather+compose).
// Inputs (metadata order):
//  0 actual  1 prediction  2 W  3 E  4 Sw  5 Se  6 lamb  7 row_ind
//  8 word_i_indices  9 entity_j_indices  10 sample_j_indices
// ---------------------------------------------------------------------------
extern "C" void kernel_launch(void* const* d_in, const int* in_sizes, int n_in,
                              void* d_out, int out_size) {
    const float* actual = (const float*)d_in[0];
    const float* pred   = (const float*)d_in[1];
    const float* W      = (const float*)d_in[2];
    const float* E      = (const float*)d_in[3];
    const float* Sw     = (const float*)d_in[4];
    const float* Se     = (const float*)d_in[5];
    const float* lamb   = (const float*)d_in[6];
    const int*   rowi   = (const int*)  d_in[7];
    const int*   wi     = (const int*)  d_in[8];
    const int*   ej     = (const int*)  d_in[9];
    const int*   sj     = (const int*)  d_in[10];
    float* out = (float*)d_out;

    fusedstream_k<<<NBLK, NTHR>>>(actual, pred, W, E);

    cudaLaunchAttribute pdl[1];
    pdl[0].id = cudaLaunchAttributeProgrammaticStreamSerialization;
    pdl[0].val.programmaticStreamSerializationAllowed = 1;

    {
        cudaLaunchConfig_t cfg = {};
        cfg.gridDim  = dim3(GG + 1, 1, 1);
        cfg.blockDim = dim3(NTHR, 1, 1);
        cfg.dynamicSmemBytes = 0;
        cfg.stream = (cudaStream_t)0;
        cfg.attrs = pdl;
        cfg.numAttrs = 1;
        cudaLaunchKernelEx(&cfg, gather_k, Sw, E, Se, lamb, rowi, wi, ej, sj, out);
    }
}